// round 1
// baseline (speedup 1.0000x reference)
#include <cuda_runtime.h>
#include <cstddef>

#define T_LEN  1024
#define KCNT   1024
#define HDIM   256
#define EDIM   64
#define TOPICN 100
#define EXLEN  768
#define GRUIN  201
#define NBLK_GATHER 512

// ---------------- scratch (static device globals; no allocation) ----------------
__device__ float g_v[TOPICN];
__device__ float g_kn[EDIM];
__device__ float g_beta_all[T_LEN];
__device__ float g_alpha_logits[KCNT];
__device__ float g_alpha[KCNT];
__device__ float g_beta[T_LEN];
__device__ int   g_idx[T_LEN];
__device__ float g_x[GRUIN];
__device__ float g_y[3 * HDIM];
__device__ float g_partial[NBLK_GATHER * HDIM];

// ---------------- K1: v = W_resize@ex_e + b ; kn = Wk@co_e + bk ----------------
__global__ void k1_vkn(const float* __restrict__ Wr, const float* __restrict__ br,
                       const float* __restrict__ ex,
                       const float* __restrict__ Wk, const float* __restrict__ bk,
                       const float* __restrict__ co)
{
    int row = blockIdx.x;
    int t = threadIdx.x;                     // 256 threads
    float s = 0.f;
    if (row < TOPICN) {
        const float* w = Wr + row * EXLEN;
        for (int c = t; c < EXLEN; c += 256) s += w[c] * ex[c];
    } else {
        const float* w = Wk + (row - TOPICN) * KCNT;
        for (int c = t; c < KCNT; c += 256) s += w[c] * co[c];
    }
    __shared__ float red[256];
    red[t] = s; __syncthreads();
    for (int off = 128; off > 0; off >>= 1) {
        if (t < off) red[t] += red[t + off];
        __syncthreads();
    }
    if (t == 0) {
        if (row < TOPICN) g_v[row] = red[0] + br[row];
        else              g_kn[row - TOPICN] = red[0] + bk[row - TOPICN];
    }
}

// ---------------- K2: beta_all = vs@v ; alpha_logits = km@kn (warp per row) ----
__global__ void k2_scores(const float* __restrict__ vs, const float* __restrict__ km)
{
    int warp = (blockIdx.x * blockDim.x + threadIdx.x) >> 5;
    int lane = threadIdx.x & 31;
    float s = 0.f;
    if (warp < T_LEN) {
        const float* row = vs + warp * TOPICN;
        for (int c = lane; c < TOPICN; c += 32) s += row[c] * g_v[c];
    } else {
        const float* row = km + (warp - T_LEN) * EDIM;
        for (int c = lane; c < EDIM; c += 32) s += row[c] * g_kn[c];
    }
    #pragma unroll
    for (int o = 16; o; o >>= 1) s += __shfl_down_sync(0xffffffffu, s, o);
    if (lane == 0) {
        if (warp < T_LEN) g_beta_all[warp] = s;
        else              g_alpha_logits[warp - T_LEN] = s;
    }
}

// ---------------- K3: top-k + softmax(beta), softmax(alpha), x vector ----------
__global__ void k3_select(const float* __restrict__ s_in, const int* __restrict__ kptr)
{
    __shared__ float sb[T_LEN];
    __shared__ float red[T_LEN];
    __shared__ float tv[T_LEN];
    __shared__ int   ti[T_LEN];
    int t = threadIdx.x;                     // 1024 threads
    int k = *kptr;
    if (k < 1) k = 1;
    if (k > T_LEN) k = T_LEN;

    float b = g_beta_all[t];
    sb[t] = b;
    __syncthreads();

    // rank = #{ j : b_j > b_i  or (b_j == b_i and j < i) }  (JAX top_k tie order)
    int rank = 0;
    #pragma unroll 8
    for (int j = 0; j < T_LEN; j++) {
        float bj = sb[j];
        rank += (bj > b) || (bj == b && j < t);
    }
    if (rank < k) { tv[rank] = b; ti[rank] = t; }
    __syncthreads();

    // softmax over the k selected values (tv sorted desc by construction)
    float maxv = tv[0];
    float e = (t < k) ? expf(tv[t] - maxv) : 0.f;
    red[t] = e; __syncthreads();
    for (int off = 512; off; off >>= 1) {
        if (t < off) red[t] += red[t + off];
        __syncthreads();
    }
    float denom = red[0];
    __syncthreads();
    if (t < k) { g_beta[t] = e / denom; g_idx[t] = ti[t]; }

    // alpha = softmax(km@kn) over 1024
    float al = g_alpha_logits[t];
    red[t] = al; __syncthreads();
    for (int off = 512; off; off >>= 1) {
        if (t < off) red[t] = fmaxf(red[t], red[t + off]);
        __syncthreads();
    }
    float am = red[0];
    __syncthreads();
    float ea = expf(al - am);
    red[t] = ea; __syncthreads();
    for (int off = 512; off; off >>= 1) {
        if (t < off) red[t] += red[t + off];
        __syncthreads();
    }
    float asum = red[0];
    g_alpha[t] = ea / asum;

    // x = [v*mask ; v*(1-mask) ; s]
    float sval = s_in[0];
    float mask = (sval >= 0.5f) ? 1.f : 0.f;
    if (t < TOPICN) {
        float vv = g_v[t];
        g_x[t] = vv * mask;
        g_x[TOPICN + t] = vv * (1.f - mask);
    }
    if (t == 0) g_x[2 * TOPICN] = sval;
}

// ---------------- K4: y = W_ih @ x (warp per row, 768 rows) --------------------
__global__ void k4_y(const float* __restrict__ Wih)
{
    int warp = (blockIdx.x * blockDim.x + threadIdx.x) >> 5;
    int lane = threadIdx.x & 31;
    if (warp >= 3 * HDIM) return;
    const float* row = Wih + warp * GRUIN;
    float s = 0.f;
    #pragma unroll
    for (int it = 0; it < 7; it++) {
        int c = lane + it * 32;
        if (c < GRUIN) s += row[c] * g_x[c];
    }
    #pragma unroll
    for (int o = 16; o; o >>= 1) s += __shfl_down_sync(0xffffffffu, s, o);
    if (lane == 0) g_y[warp] = s;
}

// ---------------- K5: gather-reduce of hs (64 MB -> 512x256 partials) ----------
__global__ void k5_gather(const float* __restrict__ hs, const int* __restrict__ kptr)
{
    __shared__ float s_alpha[KCNT];
    __shared__ float s_beta[T_LEN];
    __shared__ int   s_idx[T_LEN];
    int t = threadIdx.x;                     // 256
    int b = blockIdx.x;                      // 512
    int k = *kptr;
    if (k < 1) k = 1;
    if (k > T_LEN) k = T_LEN;

    for (int i = t; i < KCNT; i += 256) s_alpha[i] = g_alpha[i];
    for (int i = t; i < k; i += 256) { s_beta[i] = g_beta[i]; s_idx[i] = g_idx[i]; }
    __syncthreads();

    int P = k * KCNT;
    float acc = 0.f;
    #pragma unroll 4
    for (int p = b; p < P; p += NBLK_GATHER) {
        int j  = p >> 10;
        int kk = p & (KCNT - 1);
        float w = s_beta[j] * s_alpha[kk];
        size_t off = ((size_t)s_idx[j] * KCNT + (size_t)kk) * HDIM + t;
        acc += w * __ldg(&hs[off]);
    }
    g_partial[b * HDIM + t] = acc;
}

// ---------------- K6: GRU step (h0 @ W_hh^T fused with gates) ------------------
#define TI 64
#define TH 32
#define KC 64

__global__ void __launch_bounds__(128) k6_gru(
    const float* __restrict__ h0, const float* __restrict__ Whh,
    const float* __restrict__ bih, const float* __restrict__ bhh,
    float* __restrict__ out)
{
    __shared__ float As[TI][KC + 1];         // h0 tile
    __shared__ float Bs[3 * TH][KC + 1];     // W_hh rows for gates r/z/n
    int t  = threadIdx.x;                    // 128
    int i0 = blockIdx.x * TI;
    int hb = blockIdx.y * TH;
    int tx = t & 15, ty = t >> 4;            // tx: 16 along h (2 cols), ty: 8 along i (8 rows)

    float acc[3][8][2];
    #pragma unroll
    for (int g = 0; g < 3; g++)
        #pragma unroll
        for (int r = 0; r < 8; r++) { acc[g][r][0] = 0.f; acc[g][r][1] = 0.f; }

    for (int kc = 0; kc < HDIM; kc += KC) {
        // load A tile: 64x64
        #pragma unroll
        for (int u = 0; u < 8; u++) {
            int q = u * 128 + t;             // 0..1023
            int row = q >> 4;
            int c4  = (q & 15) * 4;
            float4 v = *reinterpret_cast<const float4*>(&h0[(i0 + row) * HDIM + kc + c4]);
            As[row][c4 + 0] = v.x; As[row][c4 + 1] = v.y;
            As[row][c4 + 2] = v.z; As[row][c4 + 3] = v.w;
        }
        // load B tiles: 96 rows x 64
        #pragma unroll
        for (int u = 0; u < 12; u++) {
            int q = u * 128 + t;             // 0..1535
            int m = q >> 4;                  // 0..95
            int c4 = (q & 15) * 4;
            int g  = m >> 5;
            int hl = m & 31;
            float4 v = *reinterpret_cast<const float4*>(&Whh[(g * HDIM + hb + hl) * HDIM + kc + c4]);
            Bs[m][c4 + 0] = v.x; Bs[m][c4 + 1] = v.y;
            Bs[m][c4 + 2] = v.z; Bs[m][c4 + 3] = v.w;
        }
        __syncthreads();
        #pragma unroll 4
        for (int kk = 0; kk < KC; kk++) {
            float a[8];
            #pragma unroll
            for (int r = 0; r < 8; r++) a[r] = As[ty * 8 + r][kk];
            float bb[3][2];
            #pragma unroll
            for (int g = 0; g < 3; g++) {
                bb[g][0] = Bs[g * TH + tx * 2 + 0][kk];
                bb[g][1] = Bs[g * TH + tx * 2 + 1][kk];
            }
            #pragma unroll
            for (int g = 0; g < 3; g++)
                #pragma unroll
                for (int r = 0; r < 8; r++) {
                    acc[g][r][0] += a[r] * bb[g][0];
                    acc[g][r][1] += a[r] * bb[g][1];
                }
        }
        __syncthreads();
    }

    // epilogue: gi = alpha_i * y + b_ih ; gates ; h_new -> out[1 + i*H + h]
    #pragma unroll
    for (int r = 0; r < 8; r++) {
        int i = i0 + ty * 8 + r;
        float al = g_alpha[i];
        #pragma unroll
        for (int c = 0; c < 2; c++) {
            int hcol = hb + tx * 2 + c;
            float gr  = fmaf(al, g_y[hcol],            bih[hcol])            + bhh[hcol]            + acc[0][r][c];
            float gz  = fmaf(al, g_y[HDIM + hcol],     bih[HDIM + hcol])     + bhh[HDIM + hcol]     + acc[1][r][c];
            float gni = fmaf(al, g_y[2 * HDIM + hcol], bih[2 * HDIM + hcol]);
            float ghn = acc[2][r][c] + bhh[2 * HDIM + hcol];
            float rg = 1.f / (1.f + expf(-gr));
            float zg = 1.f / (1.f + expf(-gz));
            float ng = tanhf(gni + rg * ghn);
            float hp = h0[i * HDIM + hcol];
            out[1 + i * HDIM + hcol] = (1.f - zg) * ng + zg * hp;
        }
    }
}

// ---------------- K7: reduce partials -> hkp ; predict_score -> out[0] ---------
__global__ void k7_finish(const float* __restrict__ Ws, const float* __restrict__ bs,
                          float* __restrict__ out)
{
    __shared__ float red[HDIM];
    int t = threadIdx.x;                     // 256
    float s = 0.f;
    for (int b = 0; b < NBLK_GATHER; b++) s += g_partial[b * HDIM + t];
    // score = Ws[0:100].v + Ws[100:356].hkp + b
    float c = Ws[TOPICN + t] * s;
    if (t < TOPICN) c += Ws[t] * g_v[t];
    red[t] = c; __syncthreads();
    for (int off = 128; off; off >>= 1) {
        if (t < off) red[t] += red[t + off];
        __syncthreads();
    }
    if (t == 0) out[0] = red[0] + bs[0];
}

// ---------------- launch -------------------------------------------------------
extern "C" void kernel_launch(void* const* d_in, const int* in_sizes, int n_in,
                              void* d_out, int out_size)
{
    const float* co  = (const float*)d_in[0];
    const float* ex  = (const float*)d_in[1];
    const float* s   = (const float*)d_in[2];
    const float* h0  = (const float*)d_in[3];
    const float* vs  = (const float*)d_in[4];
    const float* hs  = (const float*)d_in[5];
    const float* Wr  = (const float*)d_in[6];
    const float* br  = (const float*)d_in[7];
    const float* Wk  = (const float*)d_in[8];
    const float* bk  = (const float*)d_in[9];
    const float* km  = (const float*)d_in[10];
    const float* Ws  = (const float*)d_in[11];
    const float* bs  = (const float*)d_in[12];
    const float* Wih = (const float*)d_in[13];
    const float* Whh = (const float*)d_in[14];
    const float* bih = (const float*)d_in[15];
    const float* bhh = (const float*)d_in[16];
    const int*   kp  = (const int*)d_in[17];
    float* out = (float*)d_out;

    k1_vkn   <<<TOPICN + EDIM, 256>>>(Wr, br, ex, Wk, bk, co);
    k2_scores<<<(T_LEN + KCNT) / 8, 256>>>(vs, km);
    k3_select<<<1, 1024>>>(s, kp);
    k4_y     <<<(3 * HDIM) / 8, 256>>>(Wih);
    k5_gather<<<NBLK_GATHER, 256>>>(hs, kp);
    k6_gru   <<<dim3(KCNT / TI, HDIM / TH), 128>>>(h0, Whh, bih, bhh, out);
    k7_finish<<<1, 256>>>(Ws, bs, out);
}

// round 5
// speedup vs baseline: 1.7340x; 1.7340x over previous
#include <cuda_runtime.h>
#include <cstddef>

#define T_LEN  1024
#define KCNT   1024
#define HDIM   256
#define EDIM   64
#define TOPICN 100
#define EXLEN  768
#define GRUIN  201
#define NGATHER 512
#define NGRU   128

// ---------------- scratch ----------------
__device__ float g_v[TOPICN];
__device__ float g_kn[EDIM];
__device__ float g_beta_all[T_LEN];
__device__ float g_alpha_logits[KCNT];
__device__ float g_alpha[KCNT];
__device__ float g_beta[T_LEN];
__device__ int   g_idx[T_LEN];
__device__ float g_topv[T_LEN];
__device__ int   g_topi[T_LEN];
__device__ float g_y1[3 * HDIM];
__device__ float g_y2[3 * HDIM];
__device__ float g_y3[3 * HDIM];
__device__ float g_partial[NGATHER * HDIM];

// ---------------- helpers ----------------
__device__ __forceinline__ unsigned long long pk2(float x, float y) {
    unsigned long long u;
    asm("mov.b64 %0, {%1, %2};" : "=l"(u) : "f"(x), "f"(y));
    return u;
}
__device__ __forceinline__ unsigned long long fma2(unsigned long long a,
                                                   unsigned long long b,
                                                   unsigned long long c) {
    unsigned long long d;
    asm("fma.rn.f32x2 %0, %1, %2, %3;" : "=l"(d) : "l"(a), "l"(b), "l"(c));
    return d;
}
__device__ __forceinline__ void upk2(unsigned long long u, float& x, float& y) {
    asm("mov.b64 {%0, %1}, %2;" : "=f"(x), "=f"(y) : "l"(u));
}

// ---------------- kA: v = Wr@ex + br ; kn = Wk@co + bk ----------------
__global__ void kA_vkn(const float* __restrict__ Wr, const float* __restrict__ br,
                       const float* __restrict__ ex,
                       const float* __restrict__ Wk, const float* __restrict__ bk,
                       const float* __restrict__ co)
{
    int row = blockIdx.x;
    int t = threadIdx.x;                     // 256
    float s = 0.f;
    if (row < TOPICN) {
        const float* w = Wr + row * EXLEN;
        for (int c = t; c < EXLEN; c += 256) s += w[c] * ex[c];
    } else {
        const float* w = Wk + (row - TOPICN) * KCNT;
        for (int c = t; c < KCNT; c += 256) s += w[c] * co[c];
    }
    __shared__ float red[256];
    red[t] = s; __syncthreads();
    for (int off = 128; off > 0; off >>= 1) {
        if (t < off) red[t] += red[t + off];
        __syncthreads();
    }
    if (t == 0) {
        if (row < TOPICN) g_v[row] = red[0] + br[row];
        else              g_kn[row - TOPICN] = red[0] + bk[row - TOPICN];
    }
}

// ---------------- kB: beta_all, alpha_logits, y1, y2, y3 (warp per row) -------
__global__ void kB_scores(const float* __restrict__ vs, const float* __restrict__ km,
                          const float* __restrict__ Wih)
{
    int warp = (blockIdx.x * blockDim.x + threadIdx.x) >> 5;
    int lane = threadIdx.x & 31;
    float s = 0.f;
    if (warp < T_LEN) {
        const float* row = vs + warp * TOPICN;
        for (int c = lane; c < TOPICN; c += 32) s += row[c] * g_v[c];
    } else if (warp < 2048) {
        const float* row = km + (warp - T_LEN) * EDIM;
        for (int c = lane; c < EDIM; c += 32) s += row[c] * g_kn[c];
    } else if (warp < 2816) {
        int r = warp - 2048;
        const float* row = Wih + r * GRUIN;
        for (int c = lane; c < TOPICN; c += 32) s += row[c] * g_v[c];
        if (lane == 0) g_y3[r] = row[200];
    } else {
        int r = warp - 2816;
        const float* row = Wih + r * GRUIN + TOPICN;
        for (int c = lane; c < TOPICN; c += 32) s += row[c] * g_v[c];
    }
    #pragma unroll
    for (int o = 16; o; o >>= 1) s += __shfl_down_sync(0xffffffffu, s, o);
    if (lane == 0) {
        if      (warp < T_LEN) g_beta_all[warp] = s;
        else if (warp < 2048)  g_alpha_logits[warp - T_LEN] = s;
        else if (warp < 2816)  g_y1[warp - 2048] = s;
        else                   g_y2[warp - 2816] = s;
    }
}

// ---------------- kC1: ranks (warp handles 4 elements, lanes split j) ----------
__global__ void kC1_rank(const int* __restrict__ kptr)
{
    int gw = (blockIdx.x * blockDim.x + threadIdx.x) >> 5;   // 0..255
    int lane = threadIdx.x & 31;
    int i0 = gw * 4;
    float bi[4];
    #pragma unroll
    for (int m = 0; m < 4; m++) bi[m] = g_beta_all[i0 + m];
    int cnt[4] = {0, 0, 0, 0};
    #pragma unroll 4
    for (int jt = lane; jt < T_LEN; jt += 32) {
        float bj = __ldg(&g_beta_all[jt]);
        #pragma unroll
        for (int m = 0; m < 4; m++)
            cnt[m] += (bj > bi[m]) || (bj == bi[m] && jt < i0 + m);
    }
    #pragma unroll
    for (int m = 0; m < 4; m++) {
        #pragma unroll
        for (int o = 16; o; o >>= 1) cnt[m] += __shfl_down_sync(0xffffffffu, cnt[m], o);
    }
    if (lane == 0) {
        int k = *kptr; if (k < 1) k = 1; if (k > T_LEN) k = T_LEN;
        #pragma unroll
        for (int m = 0; m < 4; m++) {
            if (cnt[m] < k) { g_topv[cnt[m]] = bi[m]; g_topi[cnt[m]] = i0 + m; }
        }
    }
}

// ---------------- kC2: softmax(beta top-k), softmax(alpha) --------------------
__global__ void kC2_softmax(const int* __restrict__ kptr)
{
    __shared__ float red[T_LEN];
    int t = threadIdx.x;                     // 1024
    int k = *kptr; if (k < 1) k = 1; if (k > T_LEN) k = T_LEN;

    float maxv = g_topv[0];                  // rank 0 == max
    float e = (t < k) ? expf(g_topv[t] - maxv) : 0.f;
    red[t] = e; __syncthreads();
    for (int off = 512; off; off >>= 1) {
        if (t < off) red[t] += red[t + off];
        __syncthreads();
    }
    float denom = red[0]; __syncthreads();
    if (t < k) { g_beta[t] = e / denom; g_idx[t] = g_topi[t]; }

    float al = g_alpha_logits[t];
    red[t] = al; __syncthreads();
    for (int off = 512; off; off >>= 1) {
        if (t < off) red[t] = fmaxf(red[t], red[t + off]);
        __syncthreads();
    }
    float am = red[0]; __syncthreads();
    float ea = expf(al - am);
    red[t] = ea; __syncthreads();
    for (int off = 512; off; off >>= 1) {
        if (t < off) red[t] += red[t + off];
        __syncthreads();
    }
    g_alpha[t] = ea / red[0];
}

// ---------------- kDE: fused GRU GEMM (blocks 0..127) + gather (128..639) -----
#define TI 64
#define TH 32
#define KC 64
#define AS_STRIDE 68
#define BS_STRIDE 98

__global__ void __launch_bounds__(256) kDE_main(
    const float* __restrict__ h0, const float* __restrict__ Whh,
    const float* __restrict__ bih, const float* __restrict__ bhh,
    const float* __restrict__ s_in, const float* __restrict__ hs,
    const int* __restrict__ kptr, float* __restrict__ out)
{
    __shared__ __align__(16) char pool[43520];
    int t = threadIdx.x;                     // 256

    if (blockIdx.x < NGRU) {
        // ================= GRU GEMM branch =================
        float (*As)[AS_STRIDE]  = reinterpret_cast<float(*)[AS_STRIDE]>(pool);
        float (*BsT)[BS_STRIDE] = reinterpret_cast<float(*)[BS_STRIDE]>(pool + TI * AS_STRIDE * 4);
        int ib = blockIdx.x & 15;            // i tile
        int jb = blockIdx.x >> 4;            // h tile
        int i0 = ib * TI;
        int hb = jb * TH;
        int tx = t & 15;                     // h pair -> cols hb+tx*2, +1
        int ty = t >> 4;                     // 0..15  -> rows i0+ty*4 .. +3

        unsigned long long acc[3][4];
        #pragma unroll
        for (int g = 0; g < 3; g++)
            #pragma unroll
            for (int r = 0; r < 4; r++) acc[g][r] = pk2(0.f, 0.f);

        for (int kc = 0; kc < HDIM; kc += KC) {
            // load A: 64 x 64
            #pragma unroll
            for (int u = 0; u < 4; u++) {
                int q = u * 256 + t;
                int row = q >> 4;
                int c4  = (q & 15) * 4;
                float4 v = *reinterpret_cast<const float4*>(&h0[(i0 + row) * HDIM + kc + c4]);
                *reinterpret_cast<float4*>(&As[row][c4]) = v;
            }
            // load B transposed: BsT[c][g*32+hl]
            #pragma unroll
            for (int u = 0; u < 6; u++) {
                int q = u * 256 + t;
                int m  = q >> 4;             // 0..95
                int c4 = (q & 15) * 4;
                int g  = m >> 5;
                int hl = m & 31;
                float4 v = *reinterpret_cast<const float4*>(&Whh[(g * HDIM + hb + hl) * HDIM + kc + c4]);
                BsT[c4 + 0][m] = v.x; BsT[c4 + 1][m] = v.y;
                BsT[c4 + 2][m] = v.z; BsT[c4 + 3][m] = v.w;
            }
            __syncthreads();
            #pragma unroll 8
            for (int kk = 0; kk < KC; kk++) {
                unsigned long long ap[4];
                #pragma unroll
                for (int r = 0; r < 4; r++) {
                    float a = As[ty * 4 + r][kk];
                    ap[r] = pk2(a, a);
                }
                unsigned long long bp[3];
                #pragma unroll
                for (int g = 0; g < 3; g++)
                    bp[g] = *reinterpret_cast<const unsigned long long*>(&BsT[kk][g * TH + tx * 2]);
                #pragma unroll
                for (int g = 0; g < 3; g++)
                    #pragma unroll
                    for (int r = 0; r < 4; r++)
                        acc[g][r] = fma2(ap[r], bp[g], acc[g][r]);
            }
            __syncthreads();
        }

        // epilogue
        float sval = s_in[0];
        float mask = (sval >= 0.5f) ? 1.f : 0.f;
        #pragma unroll
        for (int c = 0; c < 2; c++) {
            int hcol = hb + tx * 2 + c;
            float yvr = mask * g_y1[hcol]            + (1.f - mask) * g_y2[hcol]            + sval * g_y3[hcol];
            float yvz = mask * g_y1[HDIM + hcol]     + (1.f - mask) * g_y2[HDIM + hcol]     + sval * g_y3[HDIM + hcol];
            float yvn = mask * g_y1[2*HDIM + hcol]   + (1.f - mask) * g_y2[2*HDIM + hcol]   + sval * g_y3[2*HDIM + hcol];
            float br_ = bih[hcol]          + bhh[hcol];
            float bz_ = bih[HDIM + hcol]   + bhh[HDIM + hcol];
            float bin = bih[2*HDIM + hcol];
            float bhn = bhh[2*HDIM + hcol];
            #pragma unroll
            for (int r = 0; r < 4; r++) {
                int i = i0 + ty * 4 + r;
                float al = g_alpha[i];
                float a0, a1;
                float accr, accz, accn;
                upk2(acc[0][r], a0, a1); accr = c ? a1 : a0;
                upk2(acc[1][r], a0, a1); accz = c ? a1 : a0;
                upk2(acc[2][r], a0, a1); accn = c ? a1 : a0;
                float gr = fmaf(al, yvr, br_) + accr;
                float gz = fmaf(al, yvz, bz_) + accz;
                float gni = fmaf(al, yvn, bin);
                float ghn = accn + bhn;
                float rg = 1.f / (1.f + expf(-gr));
                float zg = 1.f / (1.f + expf(-gz));
                float ng = tanhf(gni + rg * ghn);
                float hp = h0[i * HDIM + hcol];
                out[1 + i * HDIM + hcol] = (1.f - zg) * ng + zg * hp;
            }
        }
    } else {
        // ================= gather branch =================
        float* s_alpha = reinterpret_cast<float*>(pool);
        float* s_beta  = reinterpret_cast<float*>(pool + 4096);
        int*   s_idx   = reinterpret_cast<int*>(pool + 8192);
        float* sred    = reinterpret_cast<float*>(pool + 12288);  // 1024 floats

        int b = blockIdx.x - NGRU;           // 0..511
        int k = *kptr; if (k < 1) k = 1; if (k > T_LEN) k = T_LEN;

        for (int i = t; i < KCNT; i += 256) s_alpha[i] = g_alpha[i];
        for (int i = t; i < k; i += 256) { s_beta[i] = g_beta[i]; s_idx[i] = g_idx[i]; }
        __syncthreads();

        int quad = t >> 6;                   // 0..3
        int h4 = (t & 63) * 4;
        float4 acc4 = make_float4(0.f, 0.f, 0.f, 0.f);
        int P = k << 10;
        int start = b * 4 + quad;
        #pragma unroll 4
        for (int p = start; p < P; p += NGATHER * 4) {
            int j  = p >> 10;
            int kk = p & (KCNT - 1);
            float w = s_beta[j] * s_alpha[kk];
            const float4* src = reinterpret_cast<const float4*>(
                &hs[((size_t)s_idx[j] * KCNT + (size_t)kk) * HDIM + h4]);
            float4 v = __ldg(src);
            acc4.x += w * v.x; acc4.y += w * v.y;
            acc4.z += w * v.z; acc4.w += w * v.w;
        }
        sred[quad * HDIM + h4 + 0] = acc4.x;
        sred[quad * HDIM + h4 + 1] = acc4.y;
        sred[quad * HDIM + h4 + 2] = acc4.z;
        sred[quad * HDIM + h4 + 3] = acc4.w;
        __syncthreads();
        if (t < HDIM) {
            float s = sred[t] + sred[HDIM + t] + sred[2 * HDIM + t] + sred[3 * HDIM + t];
            g_partial[b * HDIM + t] = s;
        }
    }
}

// ---------------- kF: reduce partials -> hkp ; score -> out[0] ----------------
__global__ void kF_finish(const float* __restrict__ Ws, const float* __restrict__ bs,
                          float* __restrict__ out)
{
    __shared__ float sm[1024];
    int t = threadIdx.x;                     // 1024
    int h = t & 255;
    int seg = t >> 8;                        // 0..3
    float s = 0.f;
    #pragma unroll 4
    for (int b = seg; b < NGATHER; b += 4) s += g_partial[b * HDIM + h];
    sm[t] = s; __syncthreads();
    float c = 0.f;
    if (t < HDIM) {
        float hkp = sm[t] + sm[HDIM + t] + sm[2 * HDIM + t] + sm[3 * HDIM + t];
        c = Ws[TOPICN + t] * hkp;
        if (t < TOPICN) c += Ws[t] * g_v[t];
    }
    __syncthreads();
    sm[t] = (t < HDIM) ? c : 0.f;
    __syncthreads();
    for (int off = 128; off; off >>= 1) {
        if (t < off) sm[t] += sm[t + off];
        __syncthreads();
    }
    if (t == 0) out[0] = sm[0] + bs[0];
}

// ---------------- launch ------------------------------------------------------
extern "C" void kernel_launch(void* const* d_in, const int* in_sizes, int n_in,
                              void* d_out, int out_size)
{
    const float* co  = (const float*)d_in[0];
    const float* ex  = (const float*)d_in[1];
    const float* s   = (const float*)d_in[2];
    const float* h0  = (const float*)d_in[3];
    const float* vs  = (const float*)d_in[4];
    const float* hs  = (const float*)d_in[5];
    const float* Wr  = (const float*)d_in[6];
    const float* br  = (const float*)d_in[7];
    const float* Wk  = (const float*)d_in[8];
    const float* bk  = (const float*)d_in[9];
    const float* km  = (const float*)d_in[10];
    const float* Ws  = (const float*)d_in[11];
    const float* bs  = (const float*)d_in[12];
    const float* Wih = (const float*)d_in[13];
    const float* Whh = (const float*)d_in[14];
    const float* bih = (const float*)d_in[15];
    const float* bhh = (const float*)d_in[16];
    const int*   kp  = (const int*)d_in[17];
    float* out = (float*)d_out;

    kA_vkn    <<<TOPICN + EDIM, 256>>>(Wr, br, ex, Wk, bk, co);
    kB_scores <<<448, 256>>>(vs, km, Wih);
    kC1_rank  <<<32, 256>>>(kp);
    kC2_softmax<<<1, 1024>>>(kp);
    kDE_main  <<<NGRU + NGATHER, 256>>>(h0, Whh, bih, bhh, s, hs, kp, out);
    kF_finish <<<1, 1024>>>(Ws, bs, out);
}

// round 6
// speedup vs baseline: 2.1948x; 1.2657x over previous
#include <cuda_runtime.h>
#include <cstddef>

#define T_LEN  1024
#define KCNT   1024
#define HDIM   256
#define EDIM   64
#define TOPICN 100
#define EXLEN  768
#define GRUIN  201
#define NGATHER 256
#define NGRU   128

// ---------------- scratch ----------------
__device__ float g_v[TOPICN];
__device__ float g_kn[EDIM];
__device__ float g_beta_all[T_LEN];
__device__ float g_alpha_logits[KCNT];
__device__ float g_topv[T_LEN];
__device__ int   g_topi[T_LEN];
__device__ float g_y1[3 * HDIM];
__device__ float g_y2[3 * HDIM];
__device__ float g_y3[3 * HDIM];
__device__ float g_partial[NGATHER * HDIM];

// ---------------- helpers ----------------
__device__ __forceinline__ unsigned long long pk2(float x, float y) {
    unsigned long long u;
    asm("mov.b64 %0, {%1, %2};" : "=l"(u) : "f"(x), "f"(y));
    return u;
}
__device__ __forceinline__ unsigned long long fma2(unsigned long long a,
                                                   unsigned long long b,
                                                   unsigned long long c) {
    unsigned long long d;
    asm("fma.rn.f32x2 %0, %1, %2, %3;" : "=l"(d) : "l"(a), "l"(b), "l"(c));
    return d;
}
__device__ __forceinline__ void upk2(unsigned long long u, float& x, float& y) {
    asm("mov.b64 {%0, %1}, %2;" : "=f"(x), "=f"(y) : "l"(u));
}

// block reductions for 256 threads (8 warps), scratch >= 8 floats
__device__ __forceinline__ float blkSum256(float v, float* scratch, int t) {
    #pragma unroll
    for (int o = 16; o; o >>= 1) v += __shfl_xor_sync(0xffffffffu, v, o);
    if ((t & 31) == 0) scratch[t >> 5] = v;
    __syncthreads();
    float r = scratch[0];
    #pragma unroll
    for (int w = 1; w < 8; w++) r += scratch[w];
    __syncthreads();
    return r;
}
__device__ __forceinline__ float blkMax256(float v, float* scratch, int t) {
    #pragma unroll
    for (int o = 16; o; o >>= 1) v = fmaxf(v, __shfl_xor_sync(0xffffffffu, v, o));
    if ((t & 31) == 0) scratch[t >> 5] = v;
    __syncthreads();
    float r = scratch[0];
    #pragma unroll
    for (int w = 1; w < 8; w++) r = fmaxf(r, scratch[w]);
    __syncthreads();
    return r;
}

// ---------------- kA: v = Wr@ex + br ; kn = Wk@co + bk ----------------
__global__ void kA_vkn(const float* __restrict__ Wr, const float* __restrict__ br,
                       const float* __restrict__ ex,
                       const float* __restrict__ Wk, const float* __restrict__ bk,
                       const float* __restrict__ co)
{
    __shared__ float scratch[8];
    int row = blockIdx.x;
    int t = threadIdx.x;                     // 256
    float s = 0.f;
    if (row < TOPICN) {
        const float* w = Wr + row * EXLEN;
        for (int c = t; c < EXLEN; c += 256) s += w[c] * ex[c];
    } else {
        const float* w = Wk + (row - TOPICN) * KCNT;
        for (int c = t; c < KCNT; c += 256) s += w[c] * co[c];
    }
    float tot = blkSum256(s, scratch, t);
    if (t == 0) {
        if (row < TOPICN) g_v[row] = tot + br[row];
        else              g_kn[row - TOPICN] = tot + bk[row - TOPICN];
    }
}

// ---------------- kB: beta_all, alpha_logits, y1, y2, y3 (warp per row) -------
__global__ void kB_scores(const float* __restrict__ vs, const float* __restrict__ km,
                          const float* __restrict__ Wih)
{
    int warp = (blockIdx.x * blockDim.x + threadIdx.x) >> 5;
    int lane = threadIdx.x & 31;
    float s = 0.f;
    if (warp < T_LEN) {
        const float* row = vs + warp * TOPICN;
        for (int c = lane; c < TOPICN; c += 32) s += row[c] * g_v[c];
    } else if (warp < 2048) {
        const float* row = km + (warp - T_LEN) * EDIM;
        for (int c = lane; c < EDIM; c += 32) s += row[c] * g_kn[c];
    } else if (warp < 2816) {
        int r = warp - 2048;
        const float* row = Wih + r * GRUIN;
        for (int c = lane; c < TOPICN; c += 32) s += row[c] * g_v[c];
        if (lane == 0) g_y3[r] = row[200];
    } else {
        int r = warp - 2816;
        const float* row = Wih + r * GRUIN + TOPICN;
        for (int c = lane; c < TOPICN; c += 32) s += row[c] * g_v[c];
    }
    #pragma unroll
    for (int o = 16; o; o >>= 1) s += __shfl_down_sync(0xffffffffu, s, o);
    if (lane == 0) {
        if      (warp < T_LEN) g_beta_all[warp] = s;
        else if (warp < 2048)  g_alpha_logits[warp - T_LEN] = s;
        else if (warp < 2816)  g_y1[warp - 2048] = s;
        else                   g_y2[warp - 2816] = s;
    }
}

// ---------------- kC1: ranks (warp handles 4 elements, float4 scan) -----------
__global__ void kC1_rank(const int* __restrict__ kptr)
{
    int gw = (blockIdx.x * blockDim.x + threadIdx.x) >> 5;   // 0..255
    int lane = threadIdx.x & 31;
    int i0 = gw * 4;
    float bi[4];
    #pragma unroll
    for (int m = 0; m < 4; m++) bi[m] = g_beta_all[i0 + m];
    int cnt[4] = {0, 0, 0, 0};
    const float4* ba4 = reinterpret_cast<const float4*>(g_beta_all);
    #pragma unroll 2
    for (int q = lane; q < T_LEN / 4; q += 32) {
        float4 b4 = __ldg(&ba4[q]);
        int j0 = q * 4;
        #pragma unroll
        for (int m = 0; m < 4; m++) {
            cnt[m] += (b4.x > bi[m]) || (b4.x == bi[m] && j0 + 0 < i0 + m);
            cnt[m] += (b4.y > bi[m]) || (b4.y == bi[m] && j0 + 1 < i0 + m);
            cnt[m] += (b4.z > bi[m]) || (b4.z == bi[m] && j0 + 2 < i0 + m);
            cnt[m] += (b4.w > bi[m]) || (b4.w == bi[m] && j0 + 3 < i0 + m);
        }
    }
    #pragma unroll
    for (int m = 0; m < 4; m++) {
        #pragma unroll
        for (int o = 16; o; o >>= 1) cnt[m] += __shfl_down_sync(0xffffffffu, cnt[m], o);
    }
    if (lane == 0) {
        int k = *kptr; if (k < 1) k = 1; if (k > T_LEN) k = T_LEN;
        #pragma unroll
        for (int m = 0; m < 4; m++) {
            if (cnt[m] < k) { g_topv[cnt[m]] = bi[m]; g_topi[cnt[m]] = i0 + m; }
        }
    }
}

// ---------------- kDE: fused GRU GEMM (0..127) + gather (128..383) ------------
#define TI 64
#define TH 32
#define KC 64
#define AS_STRIDE 68
#define BS_STRIDE 98

__global__ void __launch_bounds__(256) kDE_main(
    const float* __restrict__ h0, const float* __restrict__ Whh,
    const float* __restrict__ bih, const float* __restrict__ bhh,
    const float* __restrict__ s_in, const float* __restrict__ hs,
    const int* __restrict__ kptr, float* __restrict__ out)
{
    __shared__ __align__(16) char pool[47232];
    int t = threadIdx.x;                     // 256

    if (blockIdx.x < NGRU) {
        // ================= GRU GEMM branch =================
        float (*As)[AS_STRIDE]  = reinterpret_cast<float(*)[AS_STRIDE]>(pool);
        float (*BsT)[BS_STRIDE] = reinterpret_cast<float(*)[BS_STRIDE]>(pool + TI * AS_STRIDE * 4);
        float* s_alpha = reinterpret_cast<float*>(pool + 42496);   // 1024 floats
        float* scratch = reinterpret_cast<float*>(pool + 46592);   // 8 floats

        // local alpha softmax (replaces kC2)
        float l[4];
        #pragma unroll
        for (int j = 0; j < 4; j++) l[j] = g_alpha_logits[t + j * 256];
        float mx = fmaxf(fmaxf(l[0], l[1]), fmaxf(l[2], l[3]));
        mx = blkMax256(mx, scratch, t);
        float e[4], se = 0.f;
        #pragma unroll
        for (int j = 0; j < 4; j++) { e[j] = expf(l[j] - mx); se += e[j]; }
        se = blkSum256(se, scratch, t);
        float inv = 1.f / se;
        #pragma unroll
        for (int j = 0; j < 4; j++) s_alpha[t + j * 256] = e[j] * inv;

        int ib = blockIdx.x & 15;            // i tile
        int jb = blockIdx.x >> 4;            // h tile
        int i0 = ib * TI;
        int hb = jb * TH;
        int tx = t & 15;                     // h pair -> cols hb+tx*2, +1
        int ty = t >> 4;                     // 0..15  -> rows i0+ty*4 .. +3

        unsigned long long acc[3][4];
        #pragma unroll
        for (int g = 0; g < 3; g++)
            #pragma unroll
            for (int r = 0; r < 4; r++) acc[g][r] = pk2(0.f, 0.f);

        __syncthreads();
        for (int kc = 0; kc < HDIM; kc += KC) {
            #pragma unroll
            for (int u = 0; u < 4; u++) {
                int q = u * 256 + t;
                int row = q >> 4;
                int c4  = (q & 15) * 4;
                float4 v = *reinterpret_cast<const float4*>(&h0[(i0 + row) * HDIM + kc + c4]);
                *reinterpret_cast<float4*>(&As[row][c4]) = v;
            }
            #pragma unroll
            for (int u = 0; u < 6; u++) {
                int q = u * 256 + t;
                int m  = q >> 4;             // 0..95
                int c4 = (q & 15) * 4;
                int g  = m >> 5;
                int hl = m & 31;
                float4 v = *reinterpret_cast<const float4*>(&Whh[(g * HDIM + hb + hl) * HDIM + kc + c4]);
                BsT[c4 + 0][m] = v.x; BsT[c4 + 1][m] = v.y;
                BsT[c4 + 2][m] = v.z; BsT[c4 + 3][m] = v.w;
            }
            __syncthreads();
            #pragma unroll 8
            for (int kk = 0; kk < KC; kk++) {
                unsigned long long ap[4];
                #pragma unroll
                for (int r = 0; r < 4; r++) {
                    float a = As[ty * 4 + r][kk];
                    ap[r] = pk2(a, a);
                }
                unsigned long long bp[3];
                #pragma unroll
                for (int g = 0; g < 3; g++)
                    bp[g] = *reinterpret_cast<const unsigned long long*>(&BsT[kk][g * TH + tx * 2]);
                #pragma unroll
                for (int g = 0; g < 3; g++)
                    #pragma unroll
                    for (int r = 0; r < 4; r++)
                        acc[g][r] = fma2(ap[r], bp[g], acc[g][r]);
            }
            __syncthreads();
        }

        // epilogue
        float sval = s_in[0];
        float mask = (sval >= 0.5f) ? 1.f : 0.f;
        #pragma unroll
        for (int c = 0; c < 2; c++) {
            int hcol = hb + tx * 2 + c;
            float yvr = mask * g_y1[hcol]          + (1.f - mask) * g_y2[hcol]          + sval * g_y3[hcol];
            float yvz = mask * g_y1[HDIM + hcol]   + (1.f - mask) * g_y2[HDIM + hcol]   + sval * g_y3[HDIM + hcol];
            float yvn = mask * g_y1[2*HDIM + hcol] + (1.f - mask) * g_y2[2*HDIM + hcol] + sval * g_y3[2*HDIM + hcol];
            float br_ = bih[hcol]          + bhh[hcol];
            float bz_ = bih[HDIM + hcol]   + bhh[HDIM + hcol];
            float bin = bih[2*HDIM + hcol];
            float bhn = bhh[2*HDIM + hcol];
            #pragma unroll
            for (int r = 0; r < 4; r++) {
                int i = i0 + ty * 4 + r;
                float al = s_alpha[i];
                float a0, a1;
                float accr, accz, accn;
                upk2(acc[0][r], a0, a1); accr = c ? a1 : a0;
                upk2(acc[1][r], a0, a1); accz = c ? a1 : a0;
                upk2(acc[2][r], a0, a1); accn = c ? a1 : a0;
                float gr = fmaf(al, yvr, br_) + accr;
                float gz = fmaf(al, yvz, bz_) + accz;
                float gni = fmaf(al, yvn, bin);
                float ghn = accn + bhn;
                float rg = 1.f / (1.f + expf(-gr));
                float zg = 1.f / (1.f + expf(-gz));
                float ng = tanhf(gni + rg * ghn);
                float hp = h0[i * HDIM + hcol];
                out[1 + i * HDIM + hcol] = (1.f - zg) * ng + zg * hp;
            }
        }
    } else {
        // ================= gather branch =================
        float* s_alpha = reinterpret_cast<float*>(pool);               // 1024
        float* s_beta  = reinterpret_cast<float*>(pool + 4096);        // 1024
        int*   s_idx   = reinterpret_cast<int*>(pool + 8192);          // 1024
        float* sred    = reinterpret_cast<float*>(pool + 12288);       // 1024
        float* scratch = reinterpret_cast<float*>(pool + 16384);       // 8

        int b = blockIdx.x - NGRU;           // 0..255
        int k = *kptr; if (k < 1) k = 1; if (k > T_LEN) k = T_LEN;

        // alpha softmax
        float l[4];
        #pragma unroll
        for (int j = 0; j < 4; j++) l[j] = g_alpha_logits[t + j * 256];
        float mx = fmaxf(fmaxf(l[0], l[1]), fmaxf(l[2], l[3]));
        mx = blkMax256(mx, scratch, t);
        float e[4], se = 0.f;
        #pragma unroll
        for (int j = 0; j < 4; j++) { e[j] = expf(l[j] - mx); se += e[j]; }
        se = blkSum256(se, scratch, t);
        float inv = 1.f / se;
        #pragma unroll
        for (int j = 0; j < 4; j++) s_alpha[t + j * 256] = e[j] * inv;

        // beta softmax over top-k (g_topv[0] is the max by construction)
        float bmax = g_topv[0];
        float bsum = 0.f;
        for (int i = t; i < k; i += 256) {
            float eb = expf(g_topv[i] - bmax);
            s_beta[i] = eb;
            s_idx[i]  = g_topi[i];
            bsum += eb;
        }
        bsum = blkSum256(bsum, scratch, t);
        float binv = 1.f / bsum;
        __syncthreads();
        for (int i = t; i < k; i += 256) s_beta[i] *= binv;
        __syncthreads();

        int quad = t >> 6;                   // 0..3
        int h4 = (t & 63) * 4;
        float4 acc4 = make_float4(0.f, 0.f, 0.f, 0.f);
        int P = k << 10;
        int start = b * 4 + quad;
        #pragma unroll 8
        for (int p = start; p < P; p += NGATHER * 4) {
            int j  = p >> 10;
            int kk = p & (KCNT - 1);
            float w = s_beta[j] * s_alpha[kk];
            const float4* src = reinterpret_cast<const float4*>(
                &hs[((size_t)s_idx[j] * KCNT + (size_t)kk) * HDIM + h4]);
            float4 v = __ldcs(src);
            acc4.x += w * v.x; acc4.y += w * v.y;
            acc4.z += w * v.z; acc4.w += w * v.w;
        }
        sred[quad * HDIM + h4 + 0] = acc4.x;
        sred[quad * HDIM + h4 + 1] = acc4.y;
        sred[quad * HDIM + h4 + 2] = acc4.z;
        sred[quad * HDIM + h4 + 3] = acc4.w;
        __syncthreads();
        if (t < HDIM) {
            float s = sred[t] + sred[HDIM + t] + sred[2 * HDIM + t] + sred[3 * HDIM + t];
            g_partial[b * HDIM + t] = s;
        }
    }
}

// ---------------- kF: reduce partials -> hkp ; score -> out[0] ----------------
__global__ void kF_finish(const float* __restrict__ Ws, const float* __restrict__ bs,
                          float* __restrict__ out)
{
    __shared__ float sm[1024];
    __shared__ float scratch[32];
    int t = threadIdx.x;                     // 1024
    int h = t & 255;
    int seg = t >> 8;                        // 0..3
    float s = 0.f;
    #pragma unroll 8
    for (int b = seg; b < NGATHER; b += 4) s += g_partial[b * HDIM + h];
    sm[t] = s; __syncthreads();
    float c = 0.f;
    if (t < HDIM) {
        float hkp = sm[t] + sm[HDIM + t] + sm[2 * HDIM + t] + sm[3 * HDIM + t];
        c = Ws[TOPICN + t] * hkp;
        if (t < TOPICN) c += Ws[t] * g_v[t];
    }
    // block sum of c over 1024 threads via shuffles + 32-warp scratch
    #pragma unroll
    for (int o = 16; o; o >>= 1) c += __shfl_xor_sync(0xffffffffu, c, o);
    if ((t & 31) == 0) scratch[t >> 5] = c;
    __syncthreads();
    if (t < 32) {
        float v = scratch[t];
        #pragma unroll
        for (int o = 16; o; o >>= 1) v += __shfl_xor_sync(0xffffffffu, v, o);
        if (t == 0) out[0] = v + bs[0];
    }
}

// ---------------- launch ------------------------------------------------------
extern "C" void kernel_launch(void* const* d_in, const int* in_sizes, int n_in,
                              void* d_out, int out_size)
{
    const float* co  = (const float*)d_in[0];
    const float* ex  = (const float*)d_in[1];
    const float* s   = (const float*)d_in[2];
    const float* h0  = (const float*)d_in[3];
    const float* vs  = (const float*)d_in[4];
    const float* hs  = (const float*)d_in[5];
    const float* Wr  = (const float*)d_in[6];
    const float* br  = (const float*)d_in[7];
    const float* Wk  = (const float*)d_in[8];
    const float* bk  = (const float*)d_in[9];
    const float* km  = (const float*)d_in[10];
    const float* Ws  = (const float*)d_in[11];
    const float* bs  = (const float*)d_in[12];
    const float* Wih = (const float*)d_in[13];
    const float* Whh = (const float*)d_in[14];
    const float* bih = (const float*)d_in[15];
    const float* bhh = (const float*)d_in[16];
    const int*   kp  = (const int*)d_in[17];
    float* out = (float*)d_out;

    kA_vkn    <<<TOPICN + EDIM, 256>>>(Wr, br, ex, Wk, bk, co);
    kB_scores <<<448, 256>>>(vs, km, Wih);
    kC1_rank  <<<32, 256>>>(kp);
    kDE_main  <<<NGRU + NGATHER, 256>>>(h0, Whh, bih, bhh, s, hs, kp, out);
    kF_finish <<<1, 1024>>>(Ws, bs, out);
}

// round 7
// speedup vs baseline: 2.2914x; 1.0440x over previous
#include <cuda_runtime.h>
#include <cstddef>

#define T_LEN  1024
#define KCNT   1024
#define HDIM   256
#define EDIM   64
#define TOPICN 100
#define EXLEN  768
#define GRUIN  201
#define NGATHER 256
#define NGRU   128

// ---------------- scratch ----------------
__device__ float g_v[TOPICN];
__device__ float g_kn[EDIM];
__device__ float g_beta_all[T_LEN];
__device__ float g_alpha_logits[KCNT];
__device__ float g_topv[T_LEN];
__device__ int   g_topi[T_LEN];
__device__ float g_y1[3 * HDIM];
__device__ float g_y2[3 * HDIM];
__device__ float g_y3[3 * HDIM];
__device__ float g_partial[NGATHER * HDIM];

// ---------------- helpers ----------------
typedef unsigned long long u64;
__device__ __forceinline__ u64 pk2(float x, float y) {
    u64 u; asm("mov.b64 %0, {%1, %2};" : "=l"(u) : "f"(x), "f"(y)); return u;
}
__device__ __forceinline__ u64 fma2(u64 a, u64 b, u64 c) {
    u64 d; asm("fma.rn.f32x2 %0, %1, %2, %3;" : "=l"(d) : "l"(a), "l"(b), "l"(c)); return d;
}
__device__ __forceinline__ void upk2(u64 u, float& x, float& y) {
    asm("mov.b64 {%0, %1}, %2;" : "=f"(x), "=f"(y) : "l"(u));
}

template<int NW>
__device__ __forceinline__ float blkSum(float v, float* scratch, int t) {
    #pragma unroll
    for (int o = 16; o; o >>= 1) v += __shfl_xor_sync(0xffffffffu, v, o);
    if ((t & 31) == 0) scratch[t >> 5] = v;
    __syncthreads();
    float r = scratch[0];
    #pragma unroll
    for (int w = 1; w < NW; w++) r += scratch[w];
    __syncthreads();
    return r;
}
template<int NW>
__device__ __forceinline__ float blkMax(float v, float* scratch, int t) {
    #pragma unroll
    for (int o = 16; o; o >>= 1) v = fmaxf(v, __shfl_xor_sync(0xffffffffu, v, o));
    if ((t & 31) == 0) scratch[t >> 5] = v;
    __syncthreads();
    float r = scratch[0];
    #pragma unroll
    for (int w = 1; w < NW; w++) r = fmaxf(r, scratch[w]);
    __syncthreads();
    return r;
}

// ---------------- kA: v = Wr@ex + br ; kn = Wk@co + bk ----------------
__global__ void kA_vkn(const float* __restrict__ Wr, const float* __restrict__ br,
                       const float* __restrict__ ex,
                       const float* __restrict__ Wk, const float* __restrict__ bk,
                       const float* __restrict__ co)
{
    __shared__ float scratch[8];
    int row = blockIdx.x;
    int t = threadIdx.x;                     // 256
    float s = 0.f;
    if (row < TOPICN) {
        const float* w = Wr + row * EXLEN;
        for (int c = t; c < EXLEN; c += 256) s += w[c] * ex[c];
    } else {
        const float* w = Wk + (row - TOPICN) * KCNT;
        for (int c = t; c < KCNT; c += 256) s += w[c] * co[c];
    }
    float tot = blkSum<8>(s, scratch, t);
    if (t == 0) {
        if (row < TOPICN) g_v[row] = tot + br[row];
        else              g_kn[row - TOPICN] = tot + bk[row - TOPICN];
    }
}

// ---------------- kB: beta_all, alpha_logits, y1, y2, y3 (warp per row) -------
__global__ void kB_scores(const float* __restrict__ vs, const float* __restrict__ km,
                          const float* __restrict__ Wih)
{
    int warp = (blockIdx.x * blockDim.x + threadIdx.x) >> 5;
    int lane = threadIdx.x & 31;
    float s = 0.f;
    if (warp < T_LEN) {
        const float* row = vs + warp * TOPICN;
        for (int c = lane; c < TOPICN; c += 32) s += row[c] * g_v[c];
    } else if (warp < 2048) {
        const float* row = km + (warp - T_LEN) * EDIM;
        for (int c = lane; c < EDIM; c += 32) s += row[c] * g_kn[c];
    } else if (warp < 2816) {
        int r = warp - 2048;
        const float* row = Wih + r * GRUIN;
        for (int c = lane; c < TOPICN; c += 32) s += row[c] * g_v[c];
        if (lane == 0) g_y3[r] = row[200];
    } else {
        int r = warp - 2816;
        const float* row = Wih + r * GRUIN + TOPICN;
        for (int c = lane; c < TOPICN; c += 32) s += row[c] * g_v[c];
    }
    #pragma unroll
    for (int o = 16; o; o >>= 1) s += __shfl_down_sync(0xffffffffu, s, o);
    if (lane == 0) {
        if      (warp < T_LEN) g_beta_all[warp] = s;
        else if (warp < 2048)  g_alpha_logits[warp - T_LEN] = s;
        else if (warp < 2816)  g_y1[warp - 2048] = s;
        else                   g_y2[warp - 2816] = s;
    }
}

// ---------------- kC1: ranks (warp handles 4 elements, float4 scan) -----------
__global__ void kC1_rank(const int* __restrict__ kptr)
{
    int gw = (blockIdx.x * blockDim.x + threadIdx.x) >> 5;   // 0..255
    int lane = threadIdx.x & 31;
    int i0 = gw * 4;
    float bi[4];
    #pragma unroll
    for (int m = 0; m < 4; m++) bi[m] = g_beta_all[i0 + m];
    int cnt[4] = {0, 0, 0, 0};
    const float4* ba4 = reinterpret_cast<const float4*>(g_beta_all);
    #pragma unroll 2
    for (int q = lane; q < T_LEN / 4; q += 32) {
        float4 b4 = __ldg(&ba4[q]);
        int j0 = q * 4;
        #pragma unroll
        for (int m = 0; m < 4; m++) {
            cnt[m] += (b4.x > bi[m]) || (b4.x == bi[m] && j0 + 0 < i0 + m);
            cnt[m] += (b4.y > bi[m]) || (b4.y == bi[m] && j0 + 1 < i0 + m);
            cnt[m] += (b4.z > bi[m]) || (b4.z == bi[m] && j0 + 2 < i0 + m);
            cnt[m] += (b4.w > bi[m]) || (b4.w == bi[m] && j0 + 3 < i0 + m);
        }
    }
    #pragma unroll
    for (int m = 0; m < 4; m++) {
        #pragma unroll
        for (int o = 16; o; o >>= 1) cnt[m] += __shfl_down_sync(0xffffffffu, cnt[m], o);
    }
    if (lane == 0) {
        int k = *kptr; if (k < 1) k = 1; if (k > T_LEN) k = T_LEN;
        #pragma unroll
        for (int m = 0; m < 4; m++) {
            if (cnt[m] < k) { g_topv[cnt[m]] = bi[m]; g_topi[cnt[m]] = i0 + m; }
        }
    }
}

// ---------------- kDE: fused GRU GEMM (0..127) + gather (128..383) ------------
#define TI 64
#define TH 32
#define KC 32
#define AS_STRIDE 36

// pool layout (bytes):
//  GEMM:   As[64][36] @0 (9216) | Bp[32][96] @9216 (12288) | alpha @21504 (4096) | scratch @25600
//  gather: alpha @0 | beta @4096 | idx @8192 | sred(2048f) @12288 | scratch @20480
#define POOL_BYTES 25664

__global__ void __launch_bounds__(512) kDE_main(
    const float* __restrict__ h0, const float* __restrict__ Whh,
    const float* __restrict__ bih, const float* __restrict__ bhh,
    const float* __restrict__ s_in, const float* __restrict__ hs,
    const int* __restrict__ kptr, float* __restrict__ out)
{
    __shared__ __align__(16) char pool[POOL_BYTES];
    int t = threadIdx.x;                     // 512

    if (blockIdx.x < NGRU) {
        // ================= GRU GEMM branch (256 threads) =================
        if (t >= 256) return;
        float (*As)[AS_STRIDE] = reinterpret_cast<float(*)[AS_STRIDE]>(pool);
        float (*Bp)[96]        = reinterpret_cast<float(*)[96]>(pool + 9216);
        float* s_alpha = reinterpret_cast<float*>(pool + 21504);
        float* scratch = reinterpret_cast<float*>(pool + 25600);

        // local alpha softmax
        float l[4];
        #pragma unroll
        for (int j = 0; j < 4; j++) l[j] = g_alpha_logits[t + j * 256];
        float mx = fmaxf(fmaxf(l[0], l[1]), fmaxf(l[2], l[3]));
        mx = blkMax<8>(mx, scratch, t);
        float e[4], se = 0.f;
        #pragma unroll
        for (int j = 0; j < 4; j++) { e[j] = expf(l[j] - mx); se += e[j]; }
        se = blkSum<8>(se, scratch, t);
        float inv = 1.f / se;
        #pragma unroll
        for (int j = 0; j < 4; j++) s_alpha[t + j * 256] = e[j] * inv;

        int ib = blockIdx.x & 15;            // i tile (16)
        int jb = blockIdx.x >> 4;            // h tile (8)
        int i0 = ib * TI;
        int hb = jb * TH;
        int tx = t & 15;                     // col pair: hb + tx*2, +1
        int ty = t >> 4;                     // 0..15 -> rows i0 + ty*4 + r

        u64 acc[3][4];
        #pragma unroll
        for (int g = 0; g < 3; g++)
            #pragma unroll
            for (int r = 0; r < 4; r++) acc[g][r] = pk2(0.f, 0.f);

        __syncthreads();
        for (int kc = 0; kc < HDIM; kc += KC) {
            // A tile: 64 rows x 32 cols = 512 float4
            #pragma unroll
            for (int u = 0; u < 2; u++) {
                int q = u * 256 + t;
                int row = q >> 3;
                int c4  = (q & 7) * 4;
                float4 v = *reinterpret_cast<const float4*>(&h0[(i0 + row) * HDIM + kc + c4]);
                As[row][c4 + 0] = v.x; As[row][c4 + 1] = v.y;
                As[row][c4 + 2] = v.z; As[row][c4 + 3] = v.w;
            }
            // B tile: 96 rows x 32 cols -> col-pair-packed Bp[kk][g*16+pi][2]
            #pragma unroll
            for (int u = 0; u < 3; u++) {
                int q = u * 256 + t;         // 0..767
                int m  = q >> 3;             // 0..95
                int c4 = (q & 7) * 4;        // kk base
                int g  = m >> 5;
                int hl = m & 31;
                int fi = (g * 16 + (hl >> 1)) * 2 + (hl & 1);
                float4 v = *reinterpret_cast<const float4*>(&Whh[(g * HDIM + hb + hl) * HDIM + kc + c4]);
                Bp[c4 + 0][fi] = v.x; Bp[c4 + 1][fi] = v.y;
                Bp[c4 + 2][fi] = v.z; Bp[c4 + 3][fi] = v.w;
            }
            __syncthreads();
            #pragma unroll
            for (int kk2 = 0; kk2 < KC / 2; kk2++) {
                int kb = kk2 * 2;
                u64 bp0[3], bp1[3];
                #pragma unroll
                for (int g = 0; g < 3; g++) {
                    bp0[g] = *reinterpret_cast<const u64*>(&Bp[kb + 0][(g * 16 + tx) * 2]);
                    bp1[g] = *reinterpret_cast<const u64*>(&Bp[kb + 1][(g * 16 + tx) * 2]);
                }
                #pragma unroll
                for (int r = 0; r < 4; r++) {
                    float2 av = *reinterpret_cast<const float2*>(&As[ty * 4 + r][kb]);
                    u64 a0 = pk2(av.x, av.x);
                    u64 a1 = pk2(av.y, av.y);
                    #pragma unroll
                    for (int g = 0; g < 3; g++) {
                        acc[g][r] = fma2(a0, bp0[g], acc[g][r]);
                        acc[g][r] = fma2(a1, bp1[g], acc[g][r]);
                    }
                }
            }
            __syncthreads();
        }

        // epilogue
        float sval = s_in[0];
        float mask = (sval >= 0.5f) ? 1.f : 0.f;
        #pragma unroll
        for (int c = 0; c < 2; c++) {
            int hcol = hb + tx * 2 + c;
            float yvr = mask * g_y1[hcol]          + (1.f - mask) * g_y2[hcol]          + sval * g_y3[hcol];
            float yvz = mask * g_y1[HDIM + hcol]   + (1.f - mask) * g_y2[HDIM + hcol]   + sval * g_y3[HDIM + hcol];
            float yvn = mask * g_y1[2*HDIM + hcol] + (1.f - mask) * g_y2[2*HDIM + hcol] + sval * g_y3[2*HDIM + hcol];
            float br_ = bih[hcol]          + bhh[hcol];
            float bz_ = bih[HDIM + hcol]   + bhh[HDIM + hcol];
            float bin = bih[2*HDIM + hcol];
            float bhn = bhh[2*HDIM + hcol];
            #pragma unroll
            for (int r = 0; r < 4; r++) {
                int i = i0 + ty * 4 + r;
                float al = s_alpha[i];
                float a0, a1;
                float accr, accz, accn;
                upk2(acc[0][r], a0, a1); accr = c ? a1 : a0;
                upk2(acc[1][r], a0, a1); accz = c ? a1 : a0;
                upk2(acc[2][r], a0, a1); accn = c ? a1 : a0;
                float gr = fmaf(al, yvr, br_) + accr;
                float gz = fmaf(al, yvz, bz_) + accz;
                float gni = fmaf(al, yvn, bin);
                float ghn = accn + bhn;
                float rg = 1.f / (1.f + expf(-gr));
                float zg = 1.f / (1.f + expf(-gz));
                float ng = tanhf(gni + rg * ghn);
                float hp = h0[i * HDIM + hcol];
                out[1 + i * HDIM + hcol] = (1.f - zg) * ng + zg * hp;
            }
        }
    } else {
        // ================= gather branch (512 threads, 8 oct-streams) ==========
        float* s_alpha = reinterpret_cast<float*>(pool);               // 1024
        float* s_beta  = reinterpret_cast<float*>(pool + 4096);        // 1024
        int*   s_idx   = reinterpret_cast<int*>(pool + 8192);          // 1024
        float* sred    = reinterpret_cast<float*>(pool + 12288);       // 2048
        float* scratch = reinterpret_cast<float*>(pool + 20480);       // 16

        int b = blockIdx.x - NGRU;           // 0..255
        int k = *kptr; if (k < 1) k = 1; if (k > T_LEN) k = T_LEN;

        // alpha softmax (512 threads, 2 elems each)
        float l0 = g_alpha_logits[t], l1 = g_alpha_logits[t + 512];
        float mx = blkMax<16>(fmaxf(l0, l1), scratch, t);
        float e0 = expf(l0 - mx), e1 = expf(l1 - mx);
        float se = blkSum<16>(e0 + e1, scratch, t);
        float inv = 1.f / se;
        s_alpha[t] = e0 * inv; s_alpha[t + 512] = e1 * inv;

        // beta softmax over top-k
        float bmax = g_topv[0];
        float bsum = 0.f;
        for (int i = t; i < k; i += 512) {
            float eb = expf(g_topv[i] - bmax);
            s_beta[i] = eb;
            s_idx[i]  = g_topi[i];
            bsum += eb;
        }
        bsum = blkSum<16>(bsum, scratch, t);
        float binv = 1.f / bsum;
        __syncthreads();
        for (int i = t; i < k; i += 512) s_beta[i] *= binv;
        __syncthreads();

        int oct = t >> 6;                    // 0..7
        int h4  = (t & 63) * 4;
        int start = b * 8 + oct;             // 0..2047
        int kk = start & (KCNT - 1);         // fixed per thread
        float alk = s_alpha[kk];
        float4 acc4 = make_float4(0.f, 0.f, 0.f, 0.f);
        int P = k << 10;
        #pragma unroll 8
        for (int p = start; p < P; p += NGATHER * 8) {
            int j = p >> 10;
            float w = s_beta[j] * alk;
            const float4* src = reinterpret_cast<const float4*>(
                &hs[((size_t)s_idx[j] * KCNT + (size_t)kk) * HDIM + h4]);
            float4 v = __ldcs(src);
            acc4.x += w * v.x; acc4.y += w * v.y;
            acc4.z += w * v.z; acc4.w += w * v.w;
        }
        sred[oct * HDIM + h4 + 0] = acc4.x;
        sred[oct * HDIM + h4 + 1] = acc4.y;
        sred[oct * HDIM + h4 + 2] = acc4.z;
        sred[oct * HDIM + h4 + 3] = acc4.w;
        __syncthreads();
        if (t < HDIM) {
            float s = 0.f;
            #pragma unroll
            for (int o = 0; o < 8; o++) s += sred[o * HDIM + t];
            g_partial[b * HDIM + t] = s;
        }
    }
}

// ---------------- kF: reduce partials -> hkp ; score -> out[0] ----------------
__global__ void kF_finish(const float* __restrict__ Ws, const float* __restrict__ bs,
                          float* __restrict__ out)
{
    __shared__ float sm[1024];
    __shared__ float scratch[32];
    int t = threadIdx.x;                     // 1024
    int h = t & 255;
    int seg = t >> 8;                        // 0..3
    float s = 0.f;
    #pragma unroll 8
    for (int b = seg; b < NGATHER; b += 4) s += g_partial[b * HDIM + h];
    sm[t] = s; __syncthreads();
    float c = 0.f;
    if (t < HDIM) {
        float hkp = sm[t] + sm[HDIM + t] + sm[2 * HDIM + t] + sm[3 * HDIM + t];
        c = Ws[TOPICN + t] * hkp;
        if (t < TOPICN) c += Ws[t] * g_v[t];
    }
    #pragma unroll
    for (int o = 16; o; o >>= 1) c += __shfl_xor_sync(0xffffffffu, c, o);
    if ((t & 31) == 0) scratch[t >> 5] = c;
    __syncthreads();
    if (t < 32) {
        float v = scratch[t];
        #pragma unroll
        for (int o = 16; o; o >>= 1) v += __shfl_xor_sync(0xffffffffu, v, o);
        if (t == 0) out[0] = v + bs[0];
    }
}

// ---------------- launch ------------------------------------------------------
extern "C" void kernel_launch(void* const* d_in, const int* in_sizes, int n_in,
                              void* d_out, int out_size)
{
    const float* co  = (const float*)d_in[0];
    const float* ex  = (const float*)d_in[1];
    const float* s   = (const float*)d_in[2];
    const float* h0  = (const float*)d_in[3];
    const float* vs  = (const float*)d_in[4];
    const float* hs  = (const float*)d_in[5];
    const float* Wr  = (const float*)d_in[6];
    const float* br  = (const float*)d_in[7];
    const float* Wk  = (const float*)d_in[8];
    const float* bk  = (const float*)d_in[9];
    const float* km  = (const float*)d_in[10];
    const float* Ws  = (const float*)d_in[11];
    const float* bs  = (const float*)d_in[12];
    const float* Wih = (const float*)d_in[13];
    const float* Whh = (const float*)d_in[14];
    const float* bih = (const float*)d_in[15];
    const float* bhh = (const float*)d_in[16];
    const int*   kp  = (const int*)d_in[17];
    float* out = (float*)d_out;

    kA_vkn    <<<TOPICN + EDIM, 256>>>(Wr, br, ex, Wk, bk, co);
    kB_scores <<<448, 256>>>(vs, km, Wih);
    kC1_rank  <<<32, 256>>>(kp);
    kDE_main  <<<NGRU + NGATHER, 512>>>(h0, Whh, bih, bhh, s, hs, kp, out);
    kF_finish <<<1, 1024>>>(Ws, bs, out);
}